// round 2
// baseline (speedup 1.0000x reference)
#include <cuda_runtime.h>
#include <cstdint>
#include <math.h>

#define NIPV    256
#define NINNER  16
#define NINPUT  784
#define NDIM    64
#define TWO_PI  6.28318530717958647692f

// lse scratch for input net (allocation-free: device global)
__device__ float g_lse[NINPUT * NIPV];

__device__ __forceinline__ float fast_tanh(float x) {
    // 1 - 2/(e^{2x}+1): saturates correctly for |x| large (inf -> 1, 0 -> -1)
    float e = __expf(2.0f * x);
    return 1.0f - __fdividef(2.0f, e + 1.0f);
}

// dot of a 64-float row (shared mem, broadcast float4 loads) with a 64-reg vector
__device__ __forceinline__ float dot64(const float* __restrict__ row, const float* __restrict__ ff) {
    const float4* r4 = (const float4*)row;
    float s0 = 0.f, s1 = 0.f, s2 = 0.f, s3 = 0.f;
#pragma unroll
    for (int q = 0; q < 16; q += 4) {
        float4 a = r4[q + 0];
        s0 = fmaf(a.x, ff[4*q + 0], s0);  s0 = fmaf(a.y, ff[4*q + 1], s0);
        s0 = fmaf(a.z, ff[4*q + 2], s0);  s0 = fmaf(a.w, ff[4*q + 3], s0);
        float4 b = r4[q + 1];
        s1 = fmaf(b.x, ff[4*q + 4], s1);  s1 = fmaf(b.y, ff[4*q + 5], s1);
        s1 = fmaf(b.z, ff[4*q + 6], s1);  s1 = fmaf(b.w, ff[4*q + 7], s1);
        float4 c = r4[q + 2];
        s2 = fmaf(c.x, ff[4*q + 8], s2);  s2 = fmaf(c.y, ff[4*q + 9], s2);
        s2 = fmaf(c.z, ff[4*q +10], s2);  s2 = fmaf(c.w, ff[4*q +11], s2);
        float4 d = r4[q + 3];
        s3 = fmaf(d.x, ff[4*q +12], s3);  s3 = fmaf(d.y, ff[4*q +13], s3);
        s3 = fmaf(d.z, ff[4*q +14], s3);  s3 = fmaf(d.w, ff[4*q +15], s3);
    }
    return (s0 + s1) + (s2 + s3);
}

// ============================================================================
// Inner net: block i (0..255), thread t = j (0..255).
// logits[g,i,j] = -softplus( sum_d w2[g,d] * tanh( w1[g*64+d,:] . ff(i,j) ) )
// lse over j of (logits + log_w[j]) via block reduction; writes
// inner_param[g, j, i] = exp(logits - lse + log_w[j])
// ============================================================================
__global__ __launch_bounds__(256) void inner_kernel(
    const float* __restrict__ z, const float* __restrict__ log_w,
    const float* __restrict__ icoef,   // [2][32]
    const float* __restrict__ w1,      // [1024][64]
    const float* __restrict__ w2,      // [16][64]
    float* __restrict__ out)           // inner_param [16][256][256]
{
    __shared__ float w1s[NDIM * NDIM];       // 16 KB, one g at a time
    __shared__ float w2s[NINNER * NDIM];     // 4 KB
    __shared__ float redbuf[8];

    const int t = threadIdx.x;               // j
    const int i = blockIdx.x;
    const int lane = t & 31, warp = t >> 5;

    const float zi = z[i];
    const float zj = z[t];
    const float lw = log_w[t];

    // fourier features in registers
    float ff[NDIM];
#pragma unroll
    for (int k = 0; k < 32; k++) {
        float xp = TWO_PI * (zi * icoef[k] + zj * icoef[32 + k]);
        float s, c;
        sincosf(xp, &s, &c);
        ff[k] = c;
        ff[32 + k] = s;
    }

    // stage w2 once
    for (int idx = t; idx < NINNER * NDIM; idx += 256) w2s[idx] = w2[idx];

    float logit[NINNER];
    for (int g = 0; g < NINNER; g++) {
        __syncthreads();  // protect w1s reuse (also covers first-use of w2s)
        {   // stage w1 rows [g*64, g*64+64) : 4096 floats, coalesced float4
            const float4* src = (const float4*)(w1 + g * NDIM * NDIM);
            float4* dst = (float4*)w1s;
#pragma unroll
            for (int r = 0; r < 4; r++) dst[t + 256 * r] = src[t + 256 * r];
        }
        __syncthreads();

        float acc = 0.f;
#pragma unroll 2
        for (int d = 0; d < NDIM; d++) {
            float s = dot64(w1s + d * NDIM, ff);
            acc = fmaf(w2s[g * NDIM + d], fast_tanh(s), acc);
        }
        // -softplus(acc), numerically stable
        logit[g] = -(fmaxf(acc, 0.f) + log1pf(__expf(-fabsf(acc))));
    }

    // per-g logsumexp over j (threads) + write output
    for (int g = 0; g < NINNER; g++) {
        float v = logit[g] + lw;
        float m = v;
#pragma unroll
        for (int o = 16; o > 0; o >>= 1) m = fmaxf(m, __shfl_xor_sync(0xffffffffu, m, o));
        __syncthreads();
        if (lane == 0) redbuf[warp] = m;
        __syncthreads();
        m = redbuf[0];
#pragma unroll
        for (int w = 1; w < 8; w++) m = fmaxf(m, redbuf[w]);

        float e = __expf(v - m);
#pragma unroll
        for (int o = 16; o > 0; o >>= 1) e += __shfl_xor_sync(0xffffffffu, e, o);
        __syncthreads();
        if (lane == 0) redbuf[warp] = e;
        __syncthreads();
        float ssum = redbuf[0];
#pragma unroll
        for (int w = 1; w < 8; w++) ssum += redbuf[w];

        float lse = m + logf(ssum);
        // inner_param[g, j=t, i]
        out[(size_t)g * (NIPV * NIPV) + (size_t)t * NIPV + i] = __expf(logit[g] - lse + lw);
    }
}

// ============================================================================
// Input net: block g (0..783), thread t = n (0..255).
// hi[d] = tanh( w1[g*64+d,:] . ffi(n) )   (64 regs per thread)
// logits[c] = w2[g,c,:] . hi   (c staged in 64-wide smem chunks)
// online logsumexp over c per thread; raw logits written coalesced via smem
// transpose; lse spilled to g_lse. Final subtract in sub_kernel.
// ============================================================================
__global__ __launch_bounds__(256) void input_kernel(
    const float* __restrict__ z,
    const float* __restrict__ icoef,   // [1][32]
    const float* __restrict__ w1,      // [784*64][64]
    const float* __restrict__ w2,      // [784][256][64]
    float* __restrict__ out)           // input_param region [784][256][256]
{
    extern __shared__ float sm[];
    float* w1s  = sm;             // 4096 floats
    float* w2s  = sm + 4096;      // 4096 floats (one 64-c chunk)
    float* tbuf = sm + 8192;      // 256 * 65 floats (transpose buffer)
    const int TB = 65;

    const int t = threadIdx.x;    // n
    const int g = blockIdx.x;

    const float zn = z[t];
    float ff[NDIM];
#pragma unroll
    for (int k = 0; k < 32; k++) {
        float xp = TWO_PI * zn * icoef[k];
        float s, c;
        sincosf(xp, &s, &c);
        ff[k] = c;
        ff[32 + k] = s;
    }

    {   // stage w1 for this g
        const float4* src = (const float4*)(w1 + (size_t)g * NDIM * NDIM);
        float4* dst = (float4*)w1s;
#pragma unroll
        for (int r = 0; r < 4; r++) dst[t + 256 * r] = src[t + 256 * r];
    }
    __syncthreads();

    float hi[NDIM];
#pragma unroll 2
    for (int d = 0; d < NDIM; d++)
        hi[d] = fast_tanh(dot64(w1s + d * NDIM, ff));

    float m = __int_as_float(0xff800000);  // -inf
    float ssum = 0.f;
    float* og = out + (size_t)g * (NIPV * 256);

    for (int cb = 0; cb < 256; cb += 64) {
        __syncthreads();  // protect w2s / tbuf reuse
        {   // stage w2 rows [cb, cb+64) of group g : 4096 floats
            const float4* src = (const float4*)(w2 + (size_t)g * 256 * NDIM + (size_t)cb * NDIM);
            float4* dst = (float4*)w2s;
#pragma unroll
            for (int r = 0; r < 4; r++) dst[t + 256 * r] = src[t + 256 * r];
        }
        __syncthreads();

#pragma unroll 2
        for (int c = 0; c < 64; c++) {
            float acc = dot64(w2s + c * NDIM, hi);
            tbuf[t * TB + c] = acc;
            // branchless online logsumexp over c
            float nm = fmaxf(m, acc);
            ssum = fmaf(ssum, __expf(m - nm), __expf(acc - nm));
            m = nm;
        }
        __syncthreads();

        // coalesced write: out[g, n, cb + c]
        for (int idx = t; idx < 256 * 64; idx += 256) {
            int n = idx >> 6;
            int c = idx & 63;
            og[(size_t)n * 256 + cb + c] = tbuf[n * TB + c];
        }
    }
    g_lse[g * NIPV + t] = m + logf(ssum);
}

// ============================================================================
// Final pass: input_param[g, n, c] -= lse[g, n]   (float4, fully coalesced)
// ============================================================================
__global__ __launch_bounds__(256) void sub_kernel(float* __restrict__ out)
{
    size_t idx = (size_t)blockIdx.x * blockDim.x + threadIdx.x;  // float4 index
    size_t e = idx * 4;
    if (e >= (size_t)NINPUT * NIPV * 256) return;
    float4* p = (float4*)out;
    float4 v = p[idx];
    float l = g_lse[e >> 8];   // (g*256 + n), since c < 256 and aligned
    v.x -= l; v.y -= l; v.z -= l; v.w -= l;
    p[idx] = v;
}

extern "C" void kernel_launch(void* const* d_in, const int* in_sizes, int n_in,
                              void* d_out, int out_size) {
    const float* z      = (const float*)d_in[0];
    const float* log_w  = (const float*)d_in[1];
    const float* icoef  = (const float*)d_in[2];  // inner_coeff [2][32]
    const float* iw1    = (const float*)d_in[3];  // inner_w1 [1024][64]
    const float* iw2    = (const float*)d_in[4];  // inner_w2 [16][64]
    const float* incoef = (const float*)d_in[5];  // input_coeff [1][32]
    const float* inw1   = (const float*)d_in[6];  // input_w1 [50176][64]
    const float* inw2   = (const float*)d_in[7];  // input_w2 [784][256][64]
    // d_in[8] = n_chunks (ignored, == 1)

    float* out = (float*)d_out;
    float* out_input = out + (size_t)NINNER * NIPV * NIPV;  // after inner_param

    const int SMEM_IN = (4096 + 4096 + 256 * 65) * sizeof(float);  // 99,328 B
    cudaFuncSetAttribute(input_kernel, cudaFuncAttributeMaxDynamicSharedMemorySize, SMEM_IN);

    inner_kernel<<<256, 256>>>(z, log_w, icoef, iw1, iw2, out);
    input_kernel<<<784, 256, SMEM_IN>>>(z, incoef, inw1, inw2, out_input);

    const size_t n4 = (size_t)NINPUT * NIPV * 256 / 4;  // 12,845,056
    sub_kernel<<<(unsigned)((n4 + 255) / 256), 256>>>(out_input);
}

// round 3
// speedup vs baseline: 1.2600x; 1.2600x over previous
#include <cuda_runtime.h>
#include <cstdint>
#include <math.h>

#define NIPV    256
#define NINNER  16
#define NINPUT  784
#define NDIM    64
#define TWO_PI  6.28318530717958647692f
#define NEG_INF __int_as_float(0xff800000)

// lse scratch for input net (allocation-free: device global)
__device__ float g_lse[NINPUT * NIPV];

__device__ __forceinline__ float fast_tanh(float x) {
    float e = __expf(2.0f * x);
    return 1.0f - __fdividef(2.0f, e + 1.0f);
}

// dot of a 64-float smem row (broadcast float4 loads) with a 64-reg vector
__device__ __forceinline__ float dot64(const float* __restrict__ row, const float* __restrict__ v) {
    const float4* r4 = (const float4*)row;
    float s0 = 0.f, s1 = 0.f, s2 = 0.f, s3 = 0.f;
#pragma unroll
    for (int q = 0; q < 16; q += 4) {
        float4 a = r4[q + 0];
        s0 = fmaf(a.x, v[4*q + 0], s0);  s0 = fmaf(a.y, v[4*q + 1], s0);
        s0 = fmaf(a.z, v[4*q + 2], s0);  s0 = fmaf(a.w, v[4*q + 3], s0);
        float4 b = r4[q + 1];
        s1 = fmaf(b.x, v[4*q + 4], s1);  s1 = fmaf(b.y, v[4*q + 5], s1);
        s1 = fmaf(b.z, v[4*q + 6], s1);  s1 = fmaf(b.w, v[4*q + 7], s1);
        float4 c = r4[q + 2];
        s2 = fmaf(c.x, v[4*q + 8], s2);  s2 = fmaf(c.y, v[4*q + 9], s2);
        s2 = fmaf(c.z, v[4*q +10], s2);  s2 = fmaf(c.w, v[4*q +11], s2);
        float4 d = r4[q + 3];
        s3 = fmaf(d.x, v[4*q +12], s3);  s3 = fmaf(d.y, v[4*q +13], s3);
        s3 = fmaf(d.z, v[4*q +14], s3);  s3 = fmaf(d.w, v[4*q +15], s3);
    }
    return (s0 + s1) + (s2 + s3);
}

__device__ __forceinline__ void copy4096(float* dst, const float* src, int t) {
    const float4* s4 = (const float4*)src; float4* d4 = (float4*)dst;
#pragma unroll
    for (int r = 0; r < 4; r++) d4[t + 256 * r] = s4[t + 256 * r];
}
__device__ __forceinline__ void copy2048(float* dst, const float* src, int t) {
    const float4* s4 = (const float4*)src; float4* d4 = (float4*)dst;
#pragma unroll
    for (int r = 0; r < 2; r++) d4[t + 256 * r] = s4[t + 256 * r];
}

// ============================================================================
// Inner path: block i, thread t = j. Double-buffered w1 staging, batched lse.
// smem: buf0[4096] buf1[4096] w2s[1024] vbuf[16*257] lsebuf[16]
// ============================================================================
__device__ __forceinline__ void inner_path(
    float* sm, int i,
    const float* __restrict__ z, const float* __restrict__ log_w,
    const float* __restrict__ icoef, const float* __restrict__ w1,
    const float* __restrict__ w2, float* __restrict__ out)
{
    float* w2s    = sm + 8192;
    float* vbuf   = sm + 9216;     // [16][257]
    float* lsebuf = sm + 9216 + 16 * 257;

    const int t = threadIdx.x, lane = t & 31, warp = t >> 5;
    const float zi = z[i];
    const float zj = z[t];
    const float lw = log_w[t];

    float ff[NDIM];
#pragma unroll
    for (int k = 0; k < 32; k++) {
        float xp = TWO_PI * fmaf(zi, icoef[k], zj * icoef[32 + k]);
        float s, c;
        __sincosf(xp, &s, &c);
        ff[k] = c;
        ff[32 + k] = s;
    }

    for (int idx = t; idx < NINNER * NDIM; idx += 256) w2s[idx] = w2[idx];
    copy4096(sm, w1, t);   // g=0 -> buf0

    float logit[NINNER];
    for (int g = 0; g < NINNER; g++) {
        __syncthreads();   // buffer for g ready (covers w2s on first iter)
        if (g < NINNER - 1)
            copy4096((g & 1) ? sm : sm + 4096, w1 + (g + 1) * 4096, t);  // prefetch g+1
        const float* W = (g & 1) ? sm + 4096 : sm;

        float a0 = 0.f, a1 = 0.f;
#pragma unroll 2
        for (int d = 0; d < NDIM; d += 2) {
            float s0 = dot64(W + d * NDIM, ff);
            float s1 = dot64(W + d * NDIM + NDIM, ff);
            a0 = fmaf(w2s[g * NDIM + d],     fast_tanh(s0), a0);
            a1 = fmaf(w2s[g * NDIM + d + 1], fast_tanh(s1), a1);
        }
        float acc = a0 + a1;
        logit[g] = -(fmaxf(acc, 0.f) + log1pf(__expf(-fabsf(acc))));
    }

    // batched logsumexp over j for all 16 g
#pragma unroll
    for (int g = 0; g < NINNER; g++) vbuf[g * 257 + t] = logit[g] + lw;
    __syncthreads();

    for (int gg = warp; gg < NINNER; gg += 8) {
        const float* row = vbuf + gg * 257;
        float m = NEG_INF;
#pragma unroll
        for (int k = 0; k < 8; k++) m = fmaxf(m, row[lane + 32 * k]);
#pragma unroll
        for (int o = 16; o > 0; o >>= 1) m = fmaxf(m, __shfl_xor_sync(0xffffffffu, m, o));
        float ssum = 0.f;
#pragma unroll
        for (int k = 0; k < 8; k++) ssum += __expf(row[lane + 32 * k] - m);
#pragma unroll
        for (int o = 16; o > 0; o >>= 1) ssum += __shfl_xor_sync(0xffffffffu, ssum, o);
        if (lane == 0) lsebuf[gg] = m + __logf(ssum);
    }
    __syncthreads();

#pragma unroll
    for (int g = 0; g < NINNER; g++)
        out[(size_t)g * (NIPV * NIPV) + (size_t)t * NIPV + i] =
            __expf(logit[g] - lsebuf[g] + lw);
}

// ============================================================================
// Input path: block g, thread t = n. Double-buffered 32-c w2 chunks.
// smem: w1s[4096] w2b[2*2048] tbuf[256*33]
// ============================================================================
__device__ __forceinline__ void input_path(
    float* sm, int g,
    const float* __restrict__ z, const float* __restrict__ icoef,
    const float* __restrict__ w1, const float* __restrict__ w2,
    float* __restrict__ out)
{
    float* w1s  = sm;
    float* w2b  = sm + 4096;
    float* tbuf = sm + 8192;   // [256][33]

    const int t = threadIdx.x;
    const float zn = z[t];

    float ff[NDIM];
#pragma unroll
    for (int k = 0; k < 32; k++) {
        float xp = TWO_PI * zn * icoef[k];
        float s, c;
        __sincosf(xp, &s, &c);
        ff[k] = c;
        ff[32 + k] = s;
    }

    copy4096(w1s, w1 + (size_t)g * 4096, t);
    __syncthreads();

    float hi[NDIM];
#pragma unroll 2
    for (int d = 0; d < NDIM; d++)
        hi[d] = fast_tanh(dot64(w1s + d * NDIM, ff));

    const float* w2g = w2 + (size_t)g * (256 * NDIM);
    copy2048(w2b, w2g, t);   // chunk 0

    float m = NEG_INF, ssum = 0.f;
    float* og = out + (size_t)g * (NIPV * 256);

    for (int cbi = 0; cbi < 8; cbi++) {
        __syncthreads();   // chunk cbi ready; tbuf drained from previous iter
        if (cbi < 7)
            copy2048((cbi & 1) ? w2b : w2b + 2048, w2g + (cbi + 1) * 2048, t);
        const float* W = (cbi & 1) ? w2b + 2048 : w2b;

#pragma unroll 2
        for (int c = 0; c < 32; c++) {
            float acc = dot64(W + c * NDIM, hi);
            tbuf[t * 33 + c] = acc;
            float nm = fmaxf(m, acc);
            ssum = fmaf(ssum, __expf(m - nm), __expf(acc - nm));
            m = nm;
        }
        __syncthreads();

        const int cb = cbi * 32;
#pragma unroll
        for (int r = 0; r < 32; r++) {
            int idx = t + 256 * r;
            int n = idx >> 5, c = idx & 31;
            og[(size_t)n * 256 + cb + c] = tbuf[n * 33 + c];
        }
    }
    g_lse[g * NIPV + t] = m + __logf(ssum);
}

// ============================================================================
// Merged kernel: blocks 0..255 inner (longer blocks first), 256..1039 input.
// ============================================================================
__global__ __launch_bounds__(256, 2) void mega_kernel(
    const float* __restrict__ z, const float* __restrict__ log_w,
    const float* __restrict__ icoef, const float* __restrict__ iw1,
    const float* __restrict__ iw2,
    const float* __restrict__ incoef, const float* __restrict__ inw1,
    const float* __restrict__ inw2,
    float* __restrict__ out_inner, float* __restrict__ out_input)
{
    extern __shared__ float sm[];
    if (blockIdx.x < 256)
        inner_path(sm, blockIdx.x, z, log_w, icoef, iw1, iw2, out_inner);
    else
        input_path(sm, blockIdx.x - 256, z, incoef, inw1, inw2, out_input);
}

// ============================================================================
// Final pass: input_param[g, n, c] -= lse[g, n]   (float4, fully coalesced)
// ============================================================================
__global__ __launch_bounds__(256) void sub_kernel(float* __restrict__ out)
{
    size_t idx = (size_t)blockIdx.x * blockDim.x + threadIdx.x;  // float4 index
    size_t e = idx * 4;
    if (e >= (size_t)NINPUT * NIPV * 256) return;
    float4* p = (float4*)out;
    float4 v = p[idx];
    float l = g_lse[e >> 8];   // (g*256 + n)
    v.x -= l; v.y -= l; v.z -= l; v.w -= l;
    p[idx] = v;
}

extern "C" void kernel_launch(void* const* d_in, const int* in_sizes, int n_in,
                              void* d_out, int out_size) {
    const float* z      = (const float*)d_in[0];
    const float* log_w  = (const float*)d_in[1];
    const float* icoef  = (const float*)d_in[2];  // inner_coeff [2][32]
    const float* iw1    = (const float*)d_in[3];  // inner_w1 [1024][64]
    const float* iw2    = (const float*)d_in[4];  // inner_w2 [16][64]
    const float* incoef = (const float*)d_in[5];  // input_coeff [1][32]
    const float* inw1   = (const float*)d_in[6];  // input_w1 [50176][64]
    const float* inw2   = (const float*)d_in[7];  // input_w2 [784][256][64]

    float* out = (float*)d_out;
    float* out_input = out + (size_t)NINNER * NIPV * NIPV;

    // union smem: input path = (4096 + 4096 + 256*33) floats = 66560 B
    const int SMEM = (4096 + 4096 + 256 * 33) * sizeof(float);
    cudaFuncSetAttribute(mega_kernel, cudaFuncAttributeMaxDynamicSharedMemorySize, SMEM);

    mega_kernel<<<256 + NINPUT, 256, SMEM>>>(z, log_w, icoef, iw1, iw2,
                                             incoef, inw1, inw2, out, out_input);

    const size_t n4 = (size_t)NINPUT * NIPV * 256 / 4;
    sub_kernel<<<(unsigned)((n4 + 255) / 256), 256>>>(out_input);
}

// round 4
// speedup vs baseline: 1.3548x; 1.0752x over previous
#include <cuda_runtime.h>
#include <cstdint>
#include <math.h>

#define NIPV    256
#define NINNER  16
#define NINPUT  784
#define NDIM    64
#define TWO_PI  6.28318530717958647692f
#define NEG_INF __int_as_float(0xff800000)

typedef unsigned long long u64;

// lse scratch for input net (allocation-free: device global)
__device__ float g_lse[NINPUT * NIPV];

// ---- packed f32x2 helpers (Blackwell FFMA2 path; ptxas never auto-fuses) ----
__device__ __forceinline__ u64 fma2(u64 a, u64 b, u64 c) {
    u64 d; asm("fma.rn.f32x2 %0, %1, %2, %3;" : "=l"(d) : "l"(a), "l"(b), "l"(c)); return d;
}
__device__ __forceinline__ u64 add2(u64 a, u64 b) {
    u64 d; asm("add.rn.f32x2 %0, %1, %2;" : "=l"(d) : "l"(a), "l"(b)); return d;
}
__device__ __forceinline__ u64 pack2(float lo, float hi) {
    u64 d; asm("mov.b64 %0, {%1, %2};" : "=l"(d) : "f"(lo), "f"(hi)); return d;
}
__device__ __forceinline__ float hsum2(u64 v) {
    float lo, hi; asm("mov.b64 {%0, %1}, %2;" : "=f"(lo), "=f"(hi) : "l"(v));
    return lo + hi;
}

__device__ __forceinline__ float fast_tanh(float x) {
    float e = __expf(2.0f * x);
    return 1.0f - __fdividef(2.0f, e + 1.0f);
}

// dot of a 64-float smem row (broadcast LDS.128) with 32 packed reg pairs
__device__ __forceinline__ float dot64p(const float* __restrict__ row, const u64* __restrict__ v) {
    const ulonglong2* r2 = (const ulonglong2*)row;   // rows are 256B-aligned
    u64 a0 = 0ull, a1 = 0ull, a2 = 0ull, a3 = 0ull;
#pragma unroll
    for (int q = 0; q < 16; q += 2) {
        ulonglong2 w0 = r2[q];
        a0 = fma2(w0.x, v[2*q + 0], a0);
        a1 = fma2(w0.y, v[2*q + 1], a1);
        ulonglong2 w1 = r2[q + 1];
        a2 = fma2(w1.x, v[2*q + 2], a2);
        a3 = fma2(w1.y, v[2*q + 3], a3);
    }
    return hsum2(add2(add2(a0, a1), add2(a2, a3)));
}

__device__ __forceinline__ void copy4096(float* dst, const float* src, int t) {
    const float4* s4 = (const float4*)src; float4* d4 = (float4*)dst;
#pragma unroll
    for (int r = 0; r < 4; r++) d4[t + 256 * r] = s4[t + 256 * r];
}
__device__ __forceinline__ void copy2048(float* dst, const float* src, int t) {
    const float4* s4 = (const float4*)src; float4* d4 = (float4*)dst;
#pragma unroll
    for (int r = 0; r < 2; r++) d4[t + 256 * r] = s4[t + 256 * r];
}

// ============================================================================
// Inner path: block i, thread t = j. Double-buffered w1, FFMA2 dots,
// logits streamed to smem (no register array), batched lse.
// smem: buf0[4096] buf1[4096] w2s[1024] vbuf[16*257] lsebuf[16]
// ============================================================================
__device__ __forceinline__ void inner_path(
    float* sm, int i,
    const float* __restrict__ z, const float* __restrict__ log_w,
    const float* __restrict__ icoef, const float* __restrict__ w1,
    const float* __restrict__ w2, float* __restrict__ out)
{
    float* w2s    = sm + 8192;
    float* vbuf   = sm + 9216;            // [16][257]
    float* lsebuf = sm + 9216 + 16 * 257;

    const int t = threadIdx.x, lane = t & 31, warp = t >> 5;

    // issue weight staging LDGs first so they hide under MUFU work below
    copy4096(sm, w1, t);                                   // g=0 -> buf0
    for (int idx = t; idx < NINNER * NDIM; idx += 256) w2s[idx] = w2[idx];

    const float zi = z[i];
    const float zj = z[t];
    const float lw = log_w[t];

    u64 vff[32];   // [0..15]=cos pairs, [16..31]=sin pairs
#pragma unroll
    for (int k = 0; k < 16; k++) {
        float xp0 = TWO_PI * fmaf(zi, icoef[2*k],     zj * icoef[32 + 2*k]);
        float xp1 = TWO_PI * fmaf(zi, icoef[2*k + 1], zj * icoef[32 + 2*k + 1]);
        float s0, c0, s1, c1;
        __sincosf(xp0, &s0, &c0);
        __sincosf(xp1, &s1, &c1);
        vff[k]      = pack2(c0, c1);
        vff[16 + k] = pack2(s0, s1);
    }

    for (int g = 0; g < NINNER; g++) {
        __syncthreads();   // buffer for g ready (covers w2s on first iter)
        if (g < NINNER - 1)
            copy4096((g & 1) ? sm : sm + 4096, w1 + (g + 1) * 4096, t);
        const float* W = (g & 1) ? sm + 4096 : sm;

        float a0 = 0.f, a1 = 0.f;
#pragma unroll 2
        for (int d = 0; d < NDIM; d += 2) {
            float s0 = dot64p(W + d * NDIM, vff);
            float s1 = dot64p(W + d * NDIM + NDIM, vff);
            a0 = fmaf(w2s[g * NDIM + d],     fast_tanh(s0), a0);
            a1 = fmaf(w2s[g * NDIM + d + 1], fast_tanh(s1), a1);
        }
        float acc = a0 + a1;
        // logit + log_w streamed to smem
        vbuf[g * 257 + t] = lw - (fmaxf(acc, 0.f) + log1pf(__expf(-fabsf(acc))));
    }
    __syncthreads();

    // batched logsumexp over j for all 16 g (one warp per 2 rows)
    for (int gg = warp; gg < NINNER; gg += 8) {
        const float* row = vbuf + gg * 257;
        float m = NEG_INF;
#pragma unroll
        for (int k = 0; k < 8; k++) m = fmaxf(m, row[lane + 32 * k]);
#pragma unroll
        for (int o = 16; o > 0; o >>= 1) m = fmaxf(m, __shfl_xor_sync(0xffffffffu, m, o));
        float ssum = 0.f;
#pragma unroll
        for (int k = 0; k < 8; k++) ssum += __expf(row[lane + 32 * k] - m);
#pragma unroll
        for (int o = 16; o > 0; o >>= 1) ssum += __shfl_xor_sync(0xffffffffu, ssum, o);
        if (lane == 0) lsebuf[gg] = m + __logf(ssum);
    }
    __syncthreads();

#pragma unroll
    for (int g = 0; g < NINNER; g++)
        out[(size_t)g * (NIPV * NIPV) + (size_t)t * NIPV + i] =
            __expf(vbuf[g * 257 + t] - lsebuf[g]);
}

// ============================================================================
// Input path: block g, thread t = n. FFMA2 dots; hi computed in two halves
// (first half parked in tbuf) to cap register pressure.
// smem: w1s[4096] w2b[2*2048] tbuf[256*33]
// ============================================================================
__device__ __forceinline__ void input_path(
    float* sm, int g,
    const float* __restrict__ z, const float* __restrict__ icoef,
    const float* __restrict__ w1, const float* __restrict__ w2,
    float* __restrict__ out)
{
    float* w1s  = sm;
    float* w2b  = sm + 4096;
    float* tbuf = sm + 8192;   // [256][33]

    const int t = threadIdx.x;
    const float* w2g = w2 + (size_t)g * (256 * NDIM);

    // stage w1 + first w2 chunk before compute so LDG latency hides
    copy4096(w1s, w1 + (size_t)g * 4096, t);
    copy2048(w2b, w2g, t);

    const float zn = z[t];
    u64 vff[32];
#pragma unroll
    for (int k = 0; k < 16; k++) {
        float s0, c0, s1, c1;
        __sincosf(TWO_PI * zn * icoef[2*k],     &s0, &c0);
        __sincosf(TWO_PI * zn * icoef[2*k + 1], &s1, &c1);
        vff[k]      = pack2(c0, c1);
        vff[16 + k] = pack2(s0, s1);
    }
    __syncthreads();

    u64 vhi[32];
    // first half of hi -> park in tbuf (per-thread slots, conflict-free)
#pragma unroll 2
    for (int d = 0; d < 32; d += 2) {
        tbuf[t * 33 + d]     = fast_tanh(dot64p(w1s + d * NDIM, vff));
        tbuf[t * 33 + d + 1] = fast_tanh(dot64p(w1s + (d + 1) * NDIM, vff));
    }
    // second half -> registers
#pragma unroll 2
    for (int d = 32; d < 64; d += 2) {
        float h0 = fast_tanh(dot64p(w1s + d * NDIM, vff));
        float h1 = fast_tanh(dot64p(w1s + (d + 1) * NDIM, vff));
        vhi[16 + (d - 32) / 2] = pack2(h0, h1);
    }
    // reload parked half (vff now dead)
#pragma unroll
    for (int k = 0; k < 16; k++)
        vhi[k] = pack2(tbuf[t * 33 + 2*k], tbuf[t * 33 + 2*k + 1]);

    float m = NEG_INF, ssum = 0.f;
    float* og = out + (size_t)g * (NIPV * 256);

    for (int cbi = 0; cbi < 8; cbi++) {
        __syncthreads();   // chunk cbi ready; tbuf drained from previous iter
        if (cbi < 7)
            copy2048((cbi & 1) ? w2b : w2b + 2048, w2g + (cbi + 1) * 2048, t);
        const float* W = (cbi & 1) ? w2b + 2048 : w2b;

#pragma unroll 2
        for (int c = 0; c < 32; c++) {
            float acc = dot64p(W + c * NDIM, vhi);
            tbuf[t * 33 + c] = acc;
            float nm = fmaxf(m, acc);
            ssum = fmaf(ssum, __expf(m - nm), __expf(acc - nm));
            m = nm;
        }
        __syncthreads();

        const int cb = cbi * 32;
#pragma unroll
        for (int r = 0; r < 32; r++) {
            int idx = t + 256 * r;
            int n = idx >> 5, c = idx & 31;
            og[(size_t)n * 256 + cb + c] = tbuf[n * 33 + c];
        }
    }
    g_lse[g * NIPV + t] = m + __logf(ssum);
}

// ============================================================================
// Merged kernel: blocks 0..255 inner (longer), 256..1039 input.
// ============================================================================
__global__ __launch_bounds__(256, 2) void mega_kernel(
    const float* __restrict__ z, const float* __restrict__ log_w,
    const float* __restrict__ icoef, const float* __restrict__ iw1,
    const float* __restrict__ iw2,
    const float* __restrict__ incoef, const float* __restrict__ inw1,
    const float* __restrict__ inw2,
    float* __restrict__ out_inner, float* __restrict__ out_input)
{
    extern __shared__ float sm[];
    if (blockIdx.x < 256)
        inner_path(sm, blockIdx.x, z, log_w, icoef, iw1, iw2, out_inner);
    else
        input_path(sm, blockIdx.x - 256, z, incoef, inw1, inw2, out_input);
}

// ============================================================================
// Final pass: input_param[g, n, c] -= lse[g, n]   (float4, fully coalesced)
// ============================================================================
__global__ __launch_bounds__(256) void sub_kernel(float* __restrict__ out)
{
    size_t idx = (size_t)blockIdx.x * blockDim.x + threadIdx.x;  // float4 index
    size_t e = idx * 4;
    if (e >= (size_t)NINPUT * NIPV * 256) return;
    float4* p = (float4*)out;
    float4 v = p[idx];
    float l = g_lse[e >> 8];   // (g*256 + n)
    v.x -= l; v.y -= l; v.z -= l; v.w -= l;
    p[idx] = v;
}

extern "C" void kernel_launch(void* const* d_in, const int* in_sizes, int n_in,
                              void* d_out, int out_size) {
    const float* z      = (const float*)d_in[0];
    const float* log_w  = (const float*)d_in[1];
    const float* icoef  = (const float*)d_in[2];  // inner_coeff [2][32]
    const float* iw1    = (const float*)d_in[3];  // inner_w1 [1024][64]
    const float* iw2    = (const float*)d_in[4];  // inner_w2 [16][64]
    const float* incoef = (const float*)d_in[5];  // input_coeff [1][32]
    const float* inw1   = (const float*)d_in[6];  // input_w1 [50176][64]
    const float* inw2   = (const float*)d_in[7];  // input_w2 [784][256][64]

    float* out = (float*)d_out;
    float* out_input = out + (size_t)NINNER * NIPV * NIPV;

    const int SMEM = (4096 + 4096 + 256 * 33) * sizeof(float);  // 66,560 B
    cudaFuncSetAttribute(mega_kernel, cudaFuncAttributeMaxDynamicSharedMemorySize, SMEM);

    mega_kernel<<<256 + NINPUT, 256, SMEM>>>(z, log_w, icoef, iw1, iw2,
                                             incoef, inw1, inw2, out, out_input);

    const size_t n4 = (size_t)NINPUT * NIPV * 256 / 4;
    sub_kernel<<<(unsigned)((n4 + 255) / 256), 256>>>(out_input);
}

// round 6
// speedup vs baseline: 3.4023x; 2.5113x over previous
#include <cuda_runtime.h>
#include <cstdint>
#include <math.h>

#define NIPV    256
#define NINNER  16
#define NINPUT  784
#define NDIM    64
#define TWO_PI  6.28318530717958647692f
#define NEG_INF __int_as_float(0xff800000)

// ---------------------------------------------------------------------------
__device__ __forceinline__ uint32_t cvt_tf32(float x) {
    uint32_t u; asm("cvt.rna.tf32.f32 %0, %1;" : "=r"(u) : "f"(x)); return u;
}
__device__ __forceinline__ void mma8(float* c, const uint32_t* a, uint32_t b0, uint32_t b1) {
    asm volatile("mma.sync.aligned.m16n8k8.row.col.f32.tf32.tf32.f32 "
        "{%0,%1,%2,%3}, {%4,%5,%6,%7}, {%8,%9}, {%0,%1,%2,%3};"
        : "+f"(c[0]), "+f"(c[1]), "+f"(c[2]), "+f"(c[3])
        : "r"(a[0]), "r"(a[1]), "r"(a[2]), "r"(a[3]), "r"(b0), "r"(b1));
}
__device__ __forceinline__ float fast_tanh(float x) {
    float e = __expf(2.0f * x);
    return 1.0f - __fdividef(2.0f, e + 1.0f);
}
__device__ __forceinline__ float softplus_f(float x) {
    return fmaxf(x, 0.f) + log1pf(__expf(-fabsf(x)));
}
// stage a 64x64 fp32 tile -> smem uints (tf32), row stride 68 (conflict-free)
__device__ __forceinline__ void stage_tile(uint32_t* dst, const float* src, int t) {
    const float4* s4 = (const float4*)src;
#pragma unroll
    for (int r = 0; r < 4; r++) {
        int f4 = t + 256 * r;
        float4 v = s4[f4];
        int row = f4 >> 4, c4 = f4 & 15;
        uint32_t* d = dst + row * 68 + c4 * 4;
        d[0] = cvt_tf32(v.x); d[1] = cvt_tf32(v.y);
        d[2] = cvt_tf32(v.z); d[3] = cvt_tf32(v.w);
    }
}
// load A fragments for 4 m-tiles at k-step ks from stride-68 tile
__device__ __forceinline__ void load_a(uint32_t a[4][4], const uint32_t* W,
                                       int ks, int gid, int tig) {
#pragma unroll
    for (int m = 0; m < 4; m++) {
        int r0 = (16 * m + gid) * 68 + ks * 8 + tig;
        a[m][0] = W[r0];            a[m][1] = W[r0 + 8 * 68];
        a[m][2] = W[r0 + 4];        a[m][3] = W[r0 + 8 * 68 + 4];
    }
}

// ===========================================================================
// Inner path: grid slice 0..511. bx -> (i = bx>>1, gh = bx&1), 8 g's each.
// smem floats: w1sA 8*4352 | w2s 512 | lws 256 | vbuf 8*260 | lseb 8
// ===========================================================================
__device__ void inner_path(float* sm, int bx,
    const float* __restrict__ z, const float* __restrict__ log_w,
    const float* __restrict__ icoef, const float* __restrict__ w1,
    const float* __restrict__ w2, float* __restrict__ out)
{
    uint32_t* w1sA = (uint32_t*)sm;
    float* w2s  = sm + 34816;
    float* lws  = sm + 35328;
    float* vbuf = sm + 35584;   // [8][260]
    float* lseb = sm + 37664;

    const int t = threadIdx.x, lane = t & 31, w = t >> 5;
    const int gid = lane >> 2, tig = lane & 3;
    const int i = bx >> 1, gh = bx & 1;

#pragma unroll 1
    for (int tl = 0; tl < 8; tl++)
        stage_tile(w1sA + tl * 4352, w1 + (size_t)(gh * 8 + tl) * 4096, t);
    for (int idx = t; idx < 512; idx += 256) w2s[idx] = w2[gh * 512 + idx];
    lws[t] = log_w[t];

    const float zi = z[i];
    float znv[4];
#pragma unroll
    for (int nf = 0; nf < 4; nf++) znv[nf] = __ldg(z + 32 * w + nf * 8 + gid);

    // B fragments: ff(k, n); k = ks*8 + tig + 4b. cos half: ks<4, sin: ks>=4.
    uint32_t bC[32], bS[32];
#pragma unroll
    for (int ksl = 0; ksl < 4; ksl++)
#pragma unroll
        for (int b = 0; b < 2; b++) {
            int f = ksl * 8 + tig + 4 * b;
            float c0 = __ldg(icoef + f), c1 = __ldg(icoef + 32 + f);
#pragma unroll
            for (int nf = 0; nf < 4; nf++) {
                float s, c;
                __sincosf(TWO_PI * fmaf(zi, c0, znv[nf] * c1), &s, &c);
                bC[ksl * 8 + b * 4 + nf] = cvt_tf32(c);
                bS[ksl * 8 + b * 4 + nf] = cvt_tf32(s);
            }
        }
    __syncthreads();

#pragma unroll 1
    for (int gl = 0; gl < 8; gl++) {
        const uint32_t* W = w1sA + gl * 4352;
        float cfr[4][4][4];
#pragma unroll
        for (int m = 0; m < 4; m++)
#pragma unroll
            for (int nf = 0; nf < 4; nf++)
#pragma unroll
                for (int jj = 0; jj < 4; jj++) cfr[m][nf][jj] = 0.f;

#pragma unroll
        for (int ks = 0; ks < 8; ks++) {
            uint32_t a[4][4];
            load_a(a, W, ks, gid, tig);
            const uint32_t* B0 = (ks < 4) ? (bC + ks * 8) : (bS + (ks - 4) * 8);
#pragma unroll
            for (int m = 0; m < 4; m++)
#pragma unroll
                for (int nf = 0; nf < 4; nf++)
                    mma8(cfr[m][nf], a[m], B0[nf], B0[4 + nf]);
        }
        // epilogue: acc_n = sum_d w2[g,d] * tanh(s[d,n])
        float pc[4][2] = {{0.f,0.f},{0.f,0.f},{0.f,0.f},{0.f,0.f}};
#pragma unroll
        for (int m = 0; m < 4; m++) {
            float w2a = w2s[gl * 64 + 16 * m + gid];
            float w2b = w2s[gl * 64 + 16 * m + gid + 8];
#pragma unroll
            for (int nf = 0; nf < 4; nf++) {
                pc[nf][0] += w2a * fast_tanh(cfr[m][nf][0]) + w2b * fast_tanh(cfr[m][nf][2]);
                pc[nf][1] += w2a * fast_tanh(cfr[m][nf][1]) + w2b * fast_tanh(cfr[m][nf][3]);
            }
        }
#pragma unroll
        for (int nf = 0; nf < 4; nf++)
#pragma unroll
            for (int j2 = 0; j2 < 2; j2++) {
#pragma unroll
                for (int o = 4; o <= 16; o <<= 1)
                    pc[nf][j2] += __shfl_xor_sync(0xffffffffu, pc[nf][j2], o);
            }
        if (gid == 0) {
#pragma unroll
            for (int nf = 0; nf < 4; nf++)
#pragma unroll
                for (int j2 = 0; j2 < 2; j2++) {
                    int n = 32 * w + nf * 8 + 2 * tig + j2;
                    vbuf[gl * 260 + n] = lws[n] - softplus_f(pc[nf][j2]);
                }
        }
    }
    __syncthreads();

    // lse over n (=j) per g: warp w handles row w
    {
        const float* row = vbuf + w * 260;
        float mx = NEG_INF;
#pragma unroll
        for (int k = 0; k < 8; k++) mx = fmaxf(mx, row[lane + 32 * k]);
#pragma unroll
        for (int o = 16; o > 0; o >>= 1) mx = fmaxf(mx, __shfl_xor_sync(0xffffffffu, mx, o));
        float ssum = 0.f;
#pragma unroll
        for (int k = 0; k < 8; k++) ssum += __expf(row[lane + 32 * k] - mx);
#pragma unroll
        for (int o = 16; o > 0; o >>= 1) ssum += __shfl_xor_sync(0xffffffffu, ssum, o);
        if (lane == 0) lseb[w] = mx + __logf(ssum);
    }
    __syncthreads();

#pragma unroll
    for (int lg = 0; lg < 8; lg++)
        out[(size_t)(gh * 8 + lg) * (NIPV * NIPV) + (size_t)t * NIPV + i] =
            __expf(vbuf[lg * 260 + t] - lseb[lg]);
}

// ===========================================================================
// Input path: block g. smem floats:
//   tiles 5*4352 (uint: 4 w2 chunks + 1 w1) | big 17408 (his then tbuf) | lseb 256
// ===========================================================================
__device__ void input_path(float* sm, int g,
    const float* __restrict__ z, const float* __restrict__ icoef,
    const float* __restrict__ w1, const float* __restrict__ w2,
    float* __restrict__ out)
{
    uint32_t* tiles = (uint32_t*)sm;
    float* big  = sm + 21760;
    float* lseb = sm + 39168;
    uint32_t* his = (uint32_t*)big;     // [64][264]
    float* tbuf = big;                  // [256][68]

    const int t = threadIdx.x, lane = t & 31, w = t >> 5;
    const int gid = lane >> 2, tig = lane & 3;

#pragma unroll 1
    for (int cb = 0; cb < 4; cb++)
        stage_tile(tiles + cb * 4352, w2 + (size_t)g * 16384 + cb * 4096, t);
    stage_tile(tiles + 4 * 4352, w1 + (size_t)g * 4096, t);

    float znv[4];
#pragma unroll
    for (int nf = 0; nf < 4; nf++) znv[nf] = __ldg(z + 32 * w + nf * 8 + gid);

    uint32_t bC[32], bS[32];
#pragma unroll
    for (int ksl = 0; ksl < 4; ksl++)
#pragma unroll
        for (int b = 0; b < 2; b++) {
            int f = ksl * 8 + tig + 4 * b;
            float cf = __ldg(icoef + f);
#pragma unroll
            for (int nf = 0; nf < 4; nf++) {
                float s, c;
                __sincosf(TWO_PI * znv[nf] * cf, &s, &c);
                bC[ksl * 8 + b * 4 + nf] = cvt_tf32(c);
                bS[ksl * 8 + b * 4 + nf] = cvt_tf32(s);
            }
        }
    __syncthreads();

    // ---- stage 1: hi[d,n] = tanh(w1g @ ff)
    {
        const uint32_t* W = tiles + 4 * 4352;
        float cfr[4][4][4];
#pragma unroll
        for (int m = 0; m < 4; m++)
#pragma unroll
            for (int nf = 0; nf < 4; nf++)
#pragma unroll
                for (int jj = 0; jj < 4; jj++) cfr[m][nf][jj] = 0.f;
#pragma unroll
        for (int ks = 0; ks < 8; ks++) {
            uint32_t a[4][4];
            load_a(a, W, ks, gid, tig);
            const uint32_t* B0 = (ks < 4) ? (bC + ks * 8) : (bS + (ks - 4) * 8);
#pragma unroll
            for (int m = 0; m < 4; m++)
#pragma unroll
                for (int nf = 0; nf < 4; nf++)
                    mma8(cfr[m][nf], a[m], B0[nf], B0[4 + nf]);
        }
#pragma unroll
        for (int m = 0; m < 4; m++)
#pragma unroll
            for (int nf = 0; nf < 4; nf++)
#pragma unroll
                for (int jj = 0; jj < 4; jj++) {
                    int d = 16 * m + gid + 8 * (jj >> 1);
                    int n = 32 * w + nf * 8 + 2 * tig + (jj & 1);
                    his[d * 264 + n] = cvt_tf32(fast_tanh(cfr[m][nf][jj]));
                }
    }
    __syncthreads();

    // B fragments for stage 2 (resident in regs)
    uint32_t bh[64];
#pragma unroll
    for (int ks = 0; ks < 8; ks++)
#pragma unroll
        for (int b = 0; b < 2; b++)
#pragma unroll
            for (int nf = 0; nf < 4; nf++)
                bh[ks * 8 + b * 4 + nf] =
                    his[(ks * 8 + tig + 4 * b) * 264 + 32 * w + nf * 8 + gid];
    __syncthreads();   // his dead; tbuf reuse safe

    float mcol[8], scol[8];
#pragma unroll
    for (int q = 0; q < 8; q++) { mcol[q] = NEG_INF; scol[q] = 0.f; }

    float* og = out + (size_t)g * (NIPV * 256);
    float4* og4 = (float4*)og;

#pragma unroll 1
    for (int cb = 0; cb < 4; cb++) {
        const uint32_t* A = tiles + cb * 4352;
        float c2[4][4][4];
#pragma unroll
        for (int m = 0; m < 4; m++)
#pragma unroll
            for (int nf = 0; nf < 4; nf++)
#pragma unroll
                for (int jj = 0; jj < 4; jj++) c2[m][nf][jj] = 0.f;
#pragma unroll
        for (int ks = 0; ks < 8; ks++) {
            uint32_t a[4][4];
            load_a(a, A, ks, gid, tig);
#pragma unroll
            for (int m = 0; m < 4; m++)
#pragma unroll
                for (int nf = 0; nf < 4; nf++)
                    mma8(c2[m][nf], a[m], bh[ks * 8 + nf], bh[ks * 8 + 4 + nf]);
        }
        // online lse per column + stash logits
#pragma unroll
        for (int nf = 0; nf < 4; nf++)
#pragma unroll
            for (int j2 = 0; j2 < 2; j2++) {
                float lm = NEG_INF;
#pragma unroll
                for (int m = 0; m < 4; m++) {
                    lm = fmaxf(lm, c2[m][nf][j2]);
                    lm = fmaxf(lm, c2[m][nf][2 + j2]);
                }
                float ls = 0.f;
#pragma unroll
                for (int m = 0; m < 4; m++) {
                    ls += __expf(c2[m][nf][j2] - lm);
                    ls += __expf(c2[m][nf][2 + j2] - lm);
                }
                int q = nf * 2 + j2;
                float nm = fmaxf(mcol[q], lm);
                scol[q] = scol[q] * __expf(mcol[q] - nm) + ls * __expf(lm - nm);
                mcol[q] = nm;
            }
#pragma unroll
        for (int m = 0; m < 4; m++)
#pragma unroll
            for (int nf = 0; nf < 4; nf++)
#pragma unroll
                for (int jj = 0; jj < 4; jj++) {
                    int cl = 16 * m + gid + 8 * (jj >> 1);
                    int n = 32 * w + nf * 8 + 2 * tig + (jj & 1);
                    tbuf[n * 68 + cl] = c2[m][nf][jj];
                }
        __syncthreads();
        // coalesced chunk write: out[g, n, cb*64 + c]
#pragma unroll
        for (int r = 0; r < 16; r++) {
            int idx = t + 256 * r;
            int n = idx >> 4, c4 = idx & 15;
            float4 v = *(float4*)(tbuf + n * 68 + c4 * 4);
            og4[(size_t)n * 64 + cb * 16 + c4] = v;
        }
        __syncthreads();
    }

    // merge (max,sum) across gid lanes
#pragma unroll
    for (int q = 0; q < 8; q++) {
#pragma unroll
        for (int o = 4; o <= 16; o <<= 1) {
            float mo = __shfl_xor_sync(0xffffffffu, mcol[q], o);
            float so = __shfl_xor_sync(0xffffffffu, scol[q], o);
            float nm = fmaxf(mcol[q], mo);
            scol[q] = scol[q] * __expf(mcol[q] - nm) + so * __expf(mo - nm);
            mcol[q] = nm;
        }
    }
    if (gid == 0) {
#pragma unroll
        for (int nf = 0; nf < 4; nf++)
#pragma unroll
            for (int j2 = 0; j2 < 2; j2++)
                lseb[32 * w + nf * 8 + 2 * tig + j2] =
                    mcol[nf * 2 + j2] + __logf(scol[nf * 2 + j2]);
    }
    __syncthreads();

    // fused log-softmax subtract (L2-hot reread)
#pragma unroll 4
    for (int r = 0; r < 64; r++) {
        int idx = t + 256 * r;
        float l = lseb[idx >> 6];
        float4 v = og4[idx];
        v.x -= l; v.y -= l; v.z -= l; v.w -= l;
        og4[idx] = v;
    }
}

// ===========================================================================
__global__ __launch_bounds__(256) void mega2_kernel(
    const float* __restrict__ z, const float* __restrict__ log_w,
    const float* __restrict__ icoef, const float* __restrict__ iw1,
    const float* __restrict__ iw2,
    const float* __restrict__ incoef, const float* __restrict__ inw1,
    const float* __restrict__ inw2,
    float* __restrict__ out_inner, float* __restrict__ out_input)
{
    extern __shared__ float sm[];
    if (blockIdx.x < 512)
        inner_path(sm, blockIdx.x, z, log_w, icoef, iw1, iw2, out_inner);
    else
        input_path(sm, blockIdx.x - 512, z, incoef, inw1, inw2, out_input);
}

extern "C" void kernel_launch(void* const* d_in, const int* in_sizes, int n_in,
                              void* d_out, int out_size) {
    const float* z      = (const float*)d_in[0];
    const float* log_w  = (const float*)d_in[1];
    const float* icoef  = (const float*)d_in[2];
    const float* iw1    = (const float*)d_in[3];
    const float* iw2    = (const float*)d_in[4];
    const float* incoef = (const float*)d_in[5];
    const float* inw1   = (const float*)d_in[6];
    const float* inw2   = (const float*)d_in[7];

    float* out = (float*)d_out;
    float* out_input = out + (size_t)NINNER * NIPV * NIPV;

    const int SMEM = 39424 * (int)sizeof(float);   // 157,696 B
    cudaFuncSetAttribute(mega2_kernel, cudaFuncAttributeMaxDynamicSharedMemorySize, SMEM);

    mega2_kernel<<<512 + NINPUT, 256, SMEM>>>(z, log_w, icoef, iw1, iw2,
                                              incoef, inw1, inw2, out, out_input);
}

// round 7
// speedup vs baseline: 3.9417x; 1.1585x over previous
#include <cuda_runtime.h>
#include <cstdint>
#include <math.h>

#define NIPV    256
#define NINNER  16
#define NINPUT  784
#define NDIM    64
#define TWO_PI  6.28318530717958647692f
#define NEG_INF __int_as_float(0xff800000)

// ---------------------------------------------------------------------------
__device__ __forceinline__ uint32_t cvt_tf32(float x) {
    uint32_t u; asm("cvt.rna.tf32.f32 %0, %1;" : "=r"(u) : "f"(x)); return u;
}
__device__ __forceinline__ void mma8(float* c, const uint32_t* a, uint32_t b0, uint32_t b1) {
    asm volatile("mma.sync.aligned.m16n8k8.row.col.f32.tf32.tf32.f32 "
        "{%0,%1,%2,%3}, {%4,%5,%6,%7}, {%8,%9}, {%0,%1,%2,%3};"
        : "+f"(c[0]), "+f"(c[1]), "+f"(c[2]), "+f"(c[3])
        : "r"(a[0]), "r"(a[1]), "r"(a[2]), "r"(a[3]), "r"(b0), "r"(b1));
}
__device__ __forceinline__ float fast_tanh(float x) {
    float e = __expf(2.0f * x);
    return 1.0f - __fdividef(2.0f, e + 1.0f);
}
__device__ __forceinline__ float softplus_f(float x) {
    return fmaxf(x, 0.f) + log1pf(__expf(-fabsf(x)));
}
// 64x64 fp32 tile staging via 16 registers (prefetch-friendly)
__device__ __forceinline__ void load_tile4(float4 v[4], const float* src, int t) {
    const float4* s4 = (const float4*)src;
#pragma unroll
    for (int r = 0; r < 4; r++) v[r] = s4[t + 256 * r];
}
__device__ __forceinline__ void store_tile4(uint32_t* dst, const float4 v[4], int t) {
#pragma unroll
    for (int r = 0; r < 4; r++) {
        int f4 = t + 256 * r;
        int row = f4 >> 4, c4 = f4 & 15;
        uint32_t* d = dst + row * 68 + c4 * 4;
        d[0] = cvt_tf32(v[r].x); d[1] = cvt_tf32(v[r].y);
        d[2] = cvt_tf32(v[r].z); d[3] = cvt_tf32(v[r].w);
    }
}
// A fragments for 4 m-tiles at k-step ks from stride-68 tile
__device__ __forceinline__ void load_a(uint32_t a[4][4], const uint32_t* W,
                                       int ks, int gid, int tig) {
#pragma unroll
    for (int m = 0; m < 4; m++) {
        int r0 = (16 * m + gid) * 68 + ks * 8 + tig;
        a[m][0] = W[r0];            a[m][1] = W[r0 + 8 * 68];
        a[m][2] = W[r0 + 4];        a[m][3] = W[r0 + 8 * 68 + 4];
    }
}

// ===========================================================================
// Inner path. smem (floats): TB(u32)4352 | ffs(u32)64*264 | w2s 512 | lws 256
//                            | vbuf 8*260 | lseb 8   -> 24,104 fl = 96,416 B
// ===========================================================================
__device__ void inner_path(float* sm, int bx,
    const float* __restrict__ z, const float* __restrict__ log_w,
    const float* __restrict__ icoef, const float* __restrict__ w1,
    const float* __restrict__ w2, float* __restrict__ out)
{
    uint32_t* TB  = (uint32_t*)sm;
    uint32_t* ffs = (uint32_t*)sm + 4352;     // [64][264]
    float* w2s  = sm + 21248;
    float* lws  = sm + 21760;
    float* vbuf = sm + 22016;                 // [8][260]
    float* lseb = sm + 24096;

    const int t = threadIdx.x, lane = t & 31, w = t >> 5;
    const int gid = lane >> 2, tig = lane & 3;
    const int i = bx >> 1, gh = bx & 1;

    float4 tr[4];
    load_tile4(tr, w1 + (size_t)(gh * 8) * 4096, t);

    const float zi = z[i], zn = z[t];
#pragma unroll
    for (int k = 0; k < 32; k++) {
        float s, c;
        __sincosf(TWO_PI * fmaf(zi, icoef[k], zn * icoef[32 + k]), &s, &c);
        ffs[k * 264 + t]        = cvt_tf32(c);
        ffs[(k + 32) * 264 + t] = cvt_tf32(s);
    }
    for (int idx = t; idx < 512; idx += 256) w2s[idx] = w2[gh * 512 + idx];
    lws[t] = log_w[t];
    store_tile4(TB, tr, t);
    __syncthreads();

#pragma unroll 1
    for (int gl = 0; gl < 8; gl++) {
        float cfr[4][4][4];
#pragma unroll
        for (int m = 0; m < 4; m++)
#pragma unroll
            for (int nf = 0; nf < 4; nf++)
#pragma unroll
                for (int jj = 0; jj < 4; jj++) cfr[m][nf][jj] = 0.f;

#pragma unroll
        for (int ks = 0; ks < 8; ks++) {
            uint32_t a[4][4];
            load_a(a, TB, ks, gid, tig);
#pragma unroll
            for (int nf = 0; nf < 4; nf++) {
                uint32_t b0 = ffs[(ks * 8 + tig)     * 264 + 32 * w + nf * 8 + gid];
                uint32_t b1 = ffs[(ks * 8 + tig + 4) * 264 + 32 * w + nf * 8 + gid];
#pragma unroll
                for (int m = 0; m < 4; m++) mma8(cfr[m][nf], a[m], b0, b1);
            }
        }
        // prefetch next tile (LDG hidden under epilogue)
        if (gl < 7) load_tile4(tr, w1 + (size_t)(gh * 8 + gl + 1) * 4096, t);

        // epilogue: acc_n = sum_d w2[g,d] * tanh(s[d,n])
        float pc[4][2] = {{0.f,0.f},{0.f,0.f},{0.f,0.f},{0.f,0.f}};
#pragma unroll
        for (int m = 0; m < 4; m++) {
            float w2a = w2s[(gl) * 64 + 16 * m + gid];
            float w2b = w2s[(gl) * 64 + 16 * m + gid + 8];
#pragma unroll
            for (int nf = 0; nf < 4; nf++) {
                pc[nf][0] += w2a * fast_tanh(cfr[m][nf][0]) + w2b * fast_tanh(cfr[m][nf][2]);
                pc[nf][1] += w2a * fast_tanh(cfr[m][nf][1]) + w2b * fast_tanh(cfr[m][nf][3]);
            }
        }
#pragma unroll
        for (int nf = 0; nf < 4; nf++)
#pragma unroll
            for (int j2 = 0; j2 < 2; j2++) {
#pragma unroll
                for (int o = 4; o <= 16; o <<= 1)
                    pc[nf][j2] += __shfl_xor_sync(0xffffffffu, pc[nf][j2], o);
            }
        if (gid == 0) {
#pragma unroll
            for (int nf = 0; nf < 4; nf++)
#pragma unroll
                for (int j2 = 0; j2 < 2; j2++) {
                    int n = 32 * w + nf * 8 + 2 * tig + j2;
                    vbuf[gl * 260 + n] = lws[n] - softplus_f(pc[nf][j2]);
                }
        }
        __syncthreads();
        if (gl < 7) store_tile4(TB, tr, t);
        __syncthreads();
    }

    // lse over n (=j) per g: warp w handles row w
    {
        const float* row = vbuf + w * 260;
        float mx = NEG_INF;
#pragma unroll
        for (int k = 0; k < 8; k++) mx = fmaxf(mx, row[lane + 32 * k]);
#pragma unroll
        for (int o = 16; o > 0; o >>= 1) mx = fmaxf(mx, __shfl_xor_sync(0xffffffffu, mx, o));
        float ssum = 0.f;
#pragma unroll
        for (int k = 0; k < 8; k++) ssum += __expf(row[lane + 32 * k] - mx);
#pragma unroll
        for (int o = 16; o > 0; o >>= 1) ssum += __shfl_xor_sync(0xffffffffu, ssum, o);
        if (lane == 0) lseb[w] = mx + __logf(ssum);
    }
    __syncthreads();

#pragma unroll
    for (int lg = 0; lg < 8; lg++)
        out[(size_t)(gh * 8 + lg) * (NIPV * NIPV) + (size_t)t * NIPV + i] =
            __expf(vbuf[lg * 260 + t] - lseb[lg]);
}

// ===========================================================================
// Input path. smem (floats): TB(u32)4352 | his(u32)64*264 | tbuf 256*20
//                            | lseb 256  -> 26,624 fl = 106,496 B
// ===========================================================================
__device__ void input_path(float* sm, int g,
    const float* __restrict__ z, const float* __restrict__ icoef,
    const float* __restrict__ w1, const float* __restrict__ w2,
    float* __restrict__ out)
{
    uint32_t* TB  = (uint32_t*)sm;
    uint32_t* his = (uint32_t*)sm + 4352;     // [64][264]
    float* tbuf = sm + 21248;                 // [256][20]
    float* lseb = sm + 26368;

    const int t = threadIdx.x, lane = t & 31, w = t >> 5;
    const int gid = lane >> 2, tig = lane & 3;
    const float* w2g = w2 + (size_t)g * 16384;

    float4 tr[4];
    load_tile4(tr, w1 + (size_t)g * 4096, t);
    store_tile4(TB, tr, t);
    __syncthreads();

    float znv[4];
#pragma unroll
    for (int nf = 0; nf < 4; nf++) znv[nf] = __ldg(z + 32 * w + nf * 8 + gid);

    // ---- stage 1: hi = tanh(w1g @ ff); B computed on the fly (sincos)
    {
        float cfr[4][4][4];
#pragma unroll
        for (int m = 0; m < 4; m++)
#pragma unroll
            for (int nf = 0; nf < 4; nf++)
#pragma unroll
                for (int jj = 0; jj < 4; jj++) cfr[m][nf][jj] = 0.f;

#pragma unroll
        for (int ks = 0; ks < 8; ks++) {
            uint32_t a[4][4];
            load_a(a, TB, ks, gid, tig);
            const int k0 = ks * 8 + tig;
            const float cf0 = __ldg(icoef + (k0 & 31));
            const float cf1 = __ldg(icoef + ((k0 + 4) & 31));
#pragma unroll
            for (int nf = 0; nf < 4; nf++) {
                float s0, c0, s1, c1;
                __sincosf(TWO_PI * znv[nf] * cf0, &s0, &c0);
                __sincosf(TWO_PI * znv[nf] * cf1, &s1, &c1);
                uint32_t b0 = cvt_tf32((ks < 4) ? c0 : s0);
                uint32_t b1 = cvt_tf32((ks < 4) ? c1 : s1);
#pragma unroll
                for (int m = 0; m < 4; m++) mma8(cfr[m][nf], a[m], b0, b1);
            }
        }
        // prefetch chunk 0 (hidden under his writes)
        load_tile4(tr, w2g, t);
#pragma unroll
        for (int m = 0; m < 4; m++)
#pragma unroll
            for (int nf = 0; nf < 4; nf++)
#pragma unroll
                for (int jj = 0; jj < 4; jj++) {
                    int d = 16 * m + gid + 8 * (jj >> 1);
                    int n = 32 * w + nf * 8 + 2 * tig + (jj & 1);
                    his[d * 264 + n] = cvt_tf32(fast_tanh(cfr[m][nf][jj]));
                }
    }
    __syncthreads();
    store_tile4(TB, tr, t);
    __syncthreads();

    float mcol[8], scol[8];
#pragma unroll
    for (int q = 0; q < 8; q++) { mcol[q] = NEG_INF; scol[q] = 0.f; }

    float* og = out + (size_t)g * (NIPV * 256);
    float4* og4 = (float4*)og;

#pragma unroll 1
    for (int cb = 0; cb < 4; cb++) {
        float c2[4][4][4];
#pragma unroll
        for (int m = 0; m < 4; m++)
#pragma unroll
            for (int nf = 0; nf < 4; nf++)
#pragma unroll
                for (int jj = 0; jj < 4; jj++) c2[m][nf][jj] = 0.f;

#pragma unroll
        for (int ks = 0; ks < 8; ks++) {
            uint32_t a[4][4];
            load_a(a, TB, ks, gid, tig);
#pragma unroll
            for (int nf = 0; nf < 4; nf++) {
                uint32_t b0 = his[(ks * 8 + tig)     * 264 + 32 * w + nf * 8 + gid];
                uint32_t b1 = his[(ks * 8 + tig + 4) * 264 + 32 * w + nf * 8 + gid];
#pragma unroll
                for (int m = 0; m < 4; m++) mma8(c2[m][nf], a[m], b0, b1);
            }
        }
        if (cb < 3) load_tile4(tr, w2g + (size_t)(cb + 1) * 4096, t);

        // online lse per column
#pragma unroll
        for (int nf = 0; nf < 4; nf++)
#pragma unroll
            for (int j2 = 0; j2 < 2; j2++) {
                float lm = NEG_INF;
#pragma unroll
                for (int m = 0; m < 4; m++) {
                    lm = fmaxf(lm, c2[m][nf][j2]);
                    lm = fmaxf(lm, c2[m][nf][2 + j2]);
                }
                float ls = 0.f;
#pragma unroll
                for (int m = 0; m < 4; m++) {
                    ls += __expf(c2[m][nf][j2] - lm);
                    ls += __expf(c2[m][nf][2 + j2] - lm);
                }
                int q = nf * 2 + j2;
                float nm = fmaxf(mcol[q], lm);
                scol[q] = scol[q] * __expf(mcol[q] - nm) + ls * __expf(lm - nm);
                mcol[q] = nm;
            }

        // write rounds: one 16-col m-tile at a time through tbuf
#pragma unroll
        for (int m = 0; m < 4; m++) {
#pragma unroll
            for (int nf = 0; nf < 4; nf++)
#pragma unroll
                for (int jj = 0; jj < 4; jj++) {
                    int cl = gid + 8 * (jj >> 1);
                    int n = 32 * w + nf * 8 + 2 * tig + (jj & 1);
                    tbuf[n * 20 + cl] = c2[m][nf][jj];
                }
            __syncthreads();
#pragma unroll
            for (int r = 0; r < 4; r++) {
                int idx = t + 256 * r;
                int n = idx >> 2, c4 = idx & 3;
                float4 v = *(float4*)(tbuf + n * 20 + c4 * 4);
                og4[(size_t)n * 64 + cb * 16 + m * 4 + c4] = v;
            }
            __syncthreads();
        }
        if (cb < 3) { store_tile4(TB, tr, t); __syncthreads(); }
    }

    // merge (max,sum) across gid lanes
#pragma unroll
    for (int q = 0; q < 8; q++) {
#pragma unroll
        for (int o = 4; o <= 16; o <<= 1) {
            float mo = __shfl_xor_sync(0xffffffffu, mcol[q], o);
            float so = __shfl_xor_sync(0xffffffffu, scol[q], o);
            float nm = fmaxf(mcol[q], mo);
            scol[q] = scol[q] * __expf(mcol[q] - nm) + so * __expf(mo - nm);
            mcol[q] = nm;
        }
    }
    if (gid == 0) {
#pragma unroll
        for (int nf = 0; nf < 4; nf++)
#pragma unroll
            for (int j2 = 0; j2 < 2; j2++)
                lseb[32 * w + nf * 8 + 2 * tig + j2] =
                    mcol[nf * 2 + j2] + __logf(scol[nf * 2 + j2]);
    }
    __syncthreads();

    // fused log-softmax subtract (L2-hot reread)
#pragma unroll 4
    for (int r = 0; r < 64; r++) {
        int idx = t + 256 * r;
        float l = lseb[idx >> 6];
        float4 v = og4[idx];
        v.x -= l; v.y -= l; v.z -= l; v.w -= l;
        og4[idx] = v;
    }
}

// ===========================================================================
__global__ __launch_bounds__(256, 2) void mega2_kernel(
    const float* __restrict__ z, const float* __restrict__ log_w,
    const float* __restrict__ icoef, const float* __restrict__ iw1,
    const float* __restrict__ iw2,
    const float* __restrict__ incoef, const float* __restrict__ inw1,
    const float* __restrict__ inw2,
    float* __restrict__ out_inner, float* __restrict__ out_input)
{
    extern __shared__ float sm[];
    if (blockIdx.x < 512)
        inner_path(sm, blockIdx.x, z, log_w, icoef, iw1, iw2, out_inner);
    else
        input_path(sm, blockIdx.x - 512, z, incoef, inw1, inw2, out_input);
}

extern "C" void kernel_launch(void* const* d_in, const int* in_sizes, int n_in,
                              void* d_out, int out_size) {
    const float* z      = (const float*)d_in[0];
    const float* log_w  = (const float*)d_in[1];
    const float* icoef  = (const float*)d_in[2];
    const float* iw1    = (const float*)d_in[3];
    const float* iw2    = (const float*)d_in[4];
    const float* incoef = (const float*)d_in[5];
    const float* inw1   = (const float*)d_in[6];
    const float* inw2   = (const float*)d_in[7];

    float* out = (float*)d_out;
    float* out_input = out + (size_t)NINNER * NIPV * NIPV;

    const int SMEM = 26624 * (int)sizeof(float);   // 106,496 B
    cudaFuncSetAttribute(mega2_kernel, cudaFuncAttributeMaxDynamicSharedMemorySize, SMEM);

    mega2_kernel<<<512 + NINPUT, 256, SMEM>>>(z, log_w, icoef, iw1, iw2,
                                              incoef, inw1, inw2, out, out_input);
}